// round 2
// baseline (speedup 1.0000x reference)
#include <cuda_runtime.h>
#include <cstdint>

// Problem: out = concat(adj_t @ x, adj_t2 @ x), N=8192, D=256, fp32.
// tcgen05 is unavailable (harness PTX target is plain sm_103, no 'a' features),
// so this uses sm_80-baseline tf32 mma.sync + cp.async double buffering.

constexpr int NN = 8192;
constexpr int DD = 256;
constexpr int BM = 64;        // M tile per CTA
constexpr int BN = 256;       // N tile = full D
constexpr int BK = 32;        // K per stage
constexpr int NITER = NN / BK;            // 256
constexpr int ASTRIDE = 36;   // A smem row stride (floats): (4m+k)%32 conflict-free
constexpr int BSTRIDE = 264;  // B smem row stride (floats): (8k+n)%32 conflict-free
constexpr int A_ELE = BM * ASTRIDE;       // 2304 floats
constexpr int B_ELE = BK * BSTRIDE;       // 8448 floats
constexpr int STG_FLT = A_ELE + B_ELE;    // 10752 floats per stage
constexpr int SMEM_BYTES = 2 * STG_FLT * 4;  // 86016 B

#define CP_ASYNC16(dst, src) \
    asm volatile("cp.async.cg.shared.global [%0], [%1], 16;" :: "r"(dst), "l"(src))

__device__ __forceinline__ uint32_t smem_u32(const void* p) {
    uint32_t a;
    asm("{ .reg .u64 t; cvta.to.shared.u64 t, %1; cvt.u32.u64 %0, t; }"
        : "=r"(a) : "l"(p));
    return a;
}

__device__ __forceinline__ uint32_t f2tf32(float f) {
    uint32_t r;
    asm("cvt.rna.tf32.f32 %0, %1;" : "=r"(r) : "f"(f));
    return r;
}

__device__ __forceinline__ void mma_tf32(float c[4], const uint32_t a[4],
                                         const uint32_t b[2]) {
    asm volatile(
        "mma.sync.aligned.m16n8k8.row.col.f32.tf32.tf32.f32 "
        "{%0,%1,%2,%3}, {%4,%5,%6,%7}, {%8,%9}, {%0,%1,%2,%3};"
        : "+f"(c[0]), "+f"(c[1]), "+f"(c[2]), "+f"(c[3])
        : "r"(a[0]), "r"(a[1]), "r"(a[2]), "r"(a[3]), "r"(b[0]), "r"(b[1]));
}

__global__ void __launch_bounds__(256, 2) h2gcn_mma(
    const float* __restrict__ adj1,
    const float* __restrict__ adj2,
    const float* __restrict__ x,
    float* __restrict__ out)
{
    extern __shared__ float smf[];
    const uint32_t smb = smem_u32(smf);

    const int t    = threadIdx.x;
    const int wid  = t >> 5;
    const int lane = t & 31;
    const int bid  = blockIdx.x;
    const int mat  = bid >> 7;                 // 0 -> adj_t, 1 -> adj_t2
    const int m0   = (bid & 127) * BM;
    const float* adj = mat ? adj2 : adj1;

    const int wm = wid & 1;      // warp M position (0..1), 32 rows each
    const int wn = wid >> 1;     // warp N position (0..3), 64 cols each
    const int gid = lane >> 2;   // groupID
    const int tig = lane & 3;    // thread in group

    // ---- cp.async chunk assignments (16B chunks) ----
    // A: 64 rows x 8 chunks = 512 -> 2 per thread
    // B: 32 rows x 64 chunks = 2048 -> 8 per thread
    const char* aptr[2];
    uint32_t    adst[2];
#pragma unroll
    for (int j = 0; j < 2; j++) {
        int id  = t + 256 * j;
        int row = id >> 3;           // 0..63
        int c   = id & 7;            // 16B column
        aptr[j] = reinterpret_cast<const char*>(adj + (size_t)(m0 + row) * NN) + c * 16;
        adst[j] = (uint32_t)((row * ASTRIDE + c * 4) * 4);
    }
    const char* bptr[8];
    uint32_t    bdst[8];
#pragma unroll
    for (int j = 0; j < 8; j++) {
        int id  = t + 256 * j;
        int row = id >> 6;           // 0..31 (k within tile)
        int c   = id & 63;           // 16B column (n)
        bptr[j] = reinterpret_cast<const char*>(x + (size_t)row * DD) + c * 16;
        bdst[j] = (uint32_t)((A_ELE + row * BSTRIDE + c * 4) * 4);
    }

    auto load_stage = [&](int buf) {
        const uint32_t sb = smb + (uint32_t)(buf * STG_FLT * 4);
#pragma unroll
        for (int j = 0; j < 2; j++) {
            CP_ASYNC16(sb + adst[j], aptr[j]);
            aptr[j] += BK * 4;                 // advance K by 32 floats
        }
#pragma unroll
        for (int j = 0; j < 8; j++) {
            CP_ASYNC16(sb + bdst[j], bptr[j]);
            bptr[j] += (size_t)BK * DD * 4;    // advance K by 32 rows of x
        }
        asm volatile("cp.async.commit_group;");
    };

    float acc[2][8][4];
#pragma unroll
    for (int mt = 0; mt < 2; mt++)
#pragma unroll
        for (int nt = 0; nt < 8; nt++)
#pragma unroll
            for (int i = 0; i < 4; i++) acc[mt][nt][i] = 0.0f;

    // Prologue
    load_stage(0);

    for (int it = 0; it < NITER; it++) {
        if (it + 1 < NITER) {
            load_stage((it + 1) & 1);
            asm volatile("cp.async.wait_group 1;");
        } else {
            asm volatile("cp.async.wait_group 0;");
        }
        __syncthreads();

        const float* sA = smf + (it & 1) * STG_FLT;
        const float* sB = sA + A_ELE;

#pragma unroll
        for (int ks = 0; ks < 4; ks++) {
            const int k = ks * 8;
            uint32_t a[2][4];
            uint32_t b[8][2];
#pragma unroll
            for (int mt = 0; mt < 2; mt++) {
                int r0 = wm * 32 + mt * 16 + gid;
                a[mt][0] = f2tf32(sA[r0 * ASTRIDE + k + tig]);
                a[mt][1] = f2tf32(sA[(r0 + 8) * ASTRIDE + k + tig]);
                a[mt][2] = f2tf32(sA[r0 * ASTRIDE + k + tig + 4]);
                a[mt][3] = f2tf32(sA[(r0 + 8) * ASTRIDE + k + tig + 4]);
            }
#pragma unroll
            for (int nt = 0; nt < 8; nt++) {
                int n = wn * 64 + nt * 8 + gid;
                b[nt][0] = f2tf32(sB[(k + tig) * BSTRIDE + n]);
                b[nt][1] = f2tf32(sB[(k + tig + 4) * BSTRIDE + n]);
            }
#pragma unroll
            for (int mt = 0; mt < 2; mt++)
#pragma unroll
                for (int nt = 0; nt < 8; nt++)
                    mma_tf32(acc[mt][nt], a[mt], b[nt]);
        }
        __syncthreads();
    }

    // Epilogue: direct float2 stores (out is [8192, 512], this matmul at col mat*256)
    const int colbase = mat * DD + wn * 64 + 2 * tig;
#pragma unroll
    for (int mt = 0; mt < 2; mt++) {
        const int row = m0 + wm * 32 + mt * 16 + gid;
#pragma unroll
        for (int nt = 0; nt < 8; nt++) {
            float* p0 = out + (size_t)row * (2 * DD) + colbase + nt * 8;
            float* p1 = p0 + 8 * (2 * DD);
            *reinterpret_cast<float2*>(p0) = make_float2(acc[mt][nt][0], acc[mt][nt][1]);
            *reinterpret_cast<float2*>(p1) = make_float2(acc[mt][nt][2], acc[mt][nt][3]);
        }
    }
}

extern "C" void kernel_launch(void* const* d_in, const int* in_sizes, int n_in,
                              void* d_out, int out_size) {
    const float* x  = nullptr;
    const float* a1 = nullptr;
    const float* a2 = nullptr;
    for (int i = 0; i < n_in; i++) {
        if (in_sizes[i] == NN * DD)  x  = (const float*)d_in[i];
        else if (!a1)                a1 = (const float*)d_in[i];
        else                         a2 = (const float*)d_in[i];
    }

    static bool attr_set = false;
    if (!attr_set) {
        cudaFuncSetAttribute(h2gcn_mma,
                             cudaFuncAttributeMaxDynamicSharedMemorySize, SMEM_BYTES);
        attr_set = true;
    }

    h2gcn_mma<<<256, 256, SMEM_BYTES>>>(a1, a2, x, (float*)d_out);
}